// round 8
// baseline (speedup 1.0000x reference)
#include <cuda_runtime.h>
#include <cuda_fp16.h>
#include <cstdint>

// ---------------------------------------------------------------------------
// BSplineKAN as one augmented fp16 GEMM (fp32 accumulate) on mma.sync:
//   A[n, i*8+j] = basis_j(clip(x[n,i]))  (j<7),  silu(clip(x[n,i]))  (j==7)
//   W[o, i*8+j] = coeff[o,i,j]           (j<7),  w_base[o,i]         (j==7)
//   out = A (8192x8192) @ W^T (1024x8192) + bias
// SW128-swizzled K-major tile images in gmem; ldmatrix.x4 fragment loads;
// persistent 128x128-tile GEMM with atomic work stealing, 2 CTAs/SM.
// ---------------------------------------------------------------------------

#define M_DIM 8192
#define N_DIM 1024
#define D_IN  1024
#define K_DIM (D_IN * 8)      // 8192 fp16 elements

#define BM 128
#define BN 128
#define BK 64                 // 64 fp16 = 128B row
#define STAGES 3
#define NK (K_DIM / BK)       // 128
#define N_TILES ((M_DIM / BM) * (N_DIM / BN))   // 512
#define GRID_CTAS 296         // 2 per SM on 148 SMs

#define A_TILE_BYTES (BM * 128)   // 16384
#define B_TILE_BYTES (BN * 128)   // 16384
#define STAGE_BYTES  (A_TILE_BYTES + B_TILE_BYTES)  // 32768
#define DYN_BYTES    (STAGES * STAGE_BYTES)         // 98304 (x2 CTAs = 192KB/SM)

__device__ __align__(128) unsigned char g_Aaug[(size_t)M_DIM * K_DIM * 2];  // 128MB
__device__ __align__(128) unsigned char g_Waug[(size_t)N_DIM * K_DIM * 2];  // 16MB
__device__ unsigned g_tile_ctr;

// ---------------------------------------------------------------------------
// Cubic B-spline basis, literal Cox-de Boor matching the reference exactly
// (EPS-guarded repeated knots; x==1 edge yields all-zero basis as in ref).
// Grid: [-1,-1,-1,-1,-0.5,0,0.5,1,1,1,1]; all reciprocals compile-time.
// ---------------------------------------------------------------------------
__device__ __forceinline__ void bspline7(float x, float b[7]) {
    const float G[11] = {-1.f,-1.f,-1.f,-1.f,-0.5f,0.f,0.5f,1.f,1.f,1.f,1.f};
    float c0[10];
    c0[0] = 0.f; c0[1] = 0.f; c0[2] = 0.f;
    c0[3] = (x >= -1.0f && x < -0.5f) ? 1.f : 0.f;
    c0[4] = (x >= -0.5f && x <  0.0f) ? 1.f : 0.f;
    c0[5] = (x >=  0.0f && x <  0.5f) ? 1.f : 0.f;
    c0[6] = (x >=  0.5f && x <  1.0f) ? 1.f : 0.f;
    c0[7] = 0.f; c0[8] = 0.f;
    c0[9] = (x == 1.0f) ? 1.f : 0.f;

    const float INV_EPS = 1e8f;
    const float H = 2.0f, O = 1.0f, T = 0.66666669f;

    const float L1[9] = {INV_EPS,INV_EPS,INV_EPS,H,H,H,H,INV_EPS,INV_EPS};
    const float R1[9] = {INV_EPS,INV_EPS,H,H,H,H,INV_EPS,INV_EPS,INV_EPS};
    float c1[9];
#pragma unroll
    for (int t = 0; t < 9; t++)
        c1[t] = ((x - G[t]) * L1[t]) * c0[t] + ((G[t + 2] - x) * R1[t]) * c0[t + 1];

    const float L2[8] = {INV_EPS,INV_EPS,H,O,O,O,H,INV_EPS};
    const float R2[8] = {INV_EPS,H,O,O,O,H,INV_EPS,INV_EPS};
    float c2[8];
#pragma unroll
    for (int t = 0; t < 8; t++)
        c2[t] = ((x - G[t]) * L2[t]) * c1[t] + ((G[t + 3] - x) * R2[t]) * c1[t + 1];

    const float L3[7] = {INV_EPS,H,O,T,T,O,H};
    const float R3[7] = {H,O,T,T,O,H,INV_EPS};
#pragma unroll
    for (int t = 0; t < 7; t++)
        b[t] = ((x - G[t]) * L3[t]) * c2[t] + ((G[t + 4] - x) * R3[t]) * c2[t + 1];
}

__device__ __forceinline__ unsigned h2(float a, float b) {
    __half2 h = __floats2half2_rn(a, b);
    return *reinterpret_cast<unsigned*>(&h);
}

// ---------------------------------------------------------------------------
// Fused pack kernel. Blocks [0, PACK_A_BLOCKS) pack A (4 dims/thread);
// remaining blocks pack W. Image: K-major fp16 rows (128B), SW128 swizzle
// u ^ ((r&7)<<4); dim i is atom (i&7) of row r in tile (mt|nt, kt).
// ---------------------------------------------------------------------------
#define PACK_A_BLOCKS ((M_DIM * D_IN / 4) / 256)    // 8192
#define PACK_W_BLOCKS ((N_DIM * D_IN / 4) / 256)    // 1024

__global__ void pack_kernel(const float* __restrict__ x,
                            const float* __restrict__ coeff,
                            const float* __restrict__ w_base) {
    if (blockIdx.x < PACK_A_BLOCKS) {
        int idx = blockIdx.x * blockDim.x + threadIdx.x;   // (n, iquad)
        int n  = idx >> 8;
        int i0 = (idx & 255) * 4;

        float4 xv = *reinterpret_cast<const float4*>(&x[(size_t)n * D_IN + i0]);
        float xc[4] = {fminf(fmaxf(xv.x, -1.f), 1.f), fminf(fmaxf(xv.y, -1.f), 1.f),
                       fminf(fmaxf(xv.z, -1.f), 1.f), fminf(fmaxf(xv.w, -1.f), 1.f)};

        int mt = n >> 7, r = n & 127;
        int kt = i0 >> 3;
        uint32_t u0 = ((uint32_t)r << 7) + ((uint32_t)(i0 & 7) << 4);
        uint32_t X  = ((uint32_t)(r & 7)) << 4;
        unsigned char* base = g_Aaug + (size_t)(mt * NK + kt) * A_TILE_BYTES;

#pragma unroll
        for (int d = 0; d < 4; d++) {
            float b[7];
            bspline7(xc[d], b);
            float s = xc[d] / (1.0f + __expf(-xc[d]));
            uint4 v = make_uint4(h2(b[0], b[1]), h2(b[2], b[3]),
                                 h2(b[4], b[5]), h2(b[6], s));
            *reinterpret_cast<uint4*>(base + ((u0 + d * 16) ^ X)) = v;
        }
    } else {
        int idx = (blockIdx.x - PACK_A_BLOCKS) * blockDim.x + threadIdx.x;
        int o  = idx >> 8;
        int i0 = (idx & 255) * 4;

        int nt = o >> 7, r = o & 127;
        int kt = i0 >> 3;
        uint32_t u0 = ((uint32_t)r << 7) + ((uint32_t)(i0 & 7) << 4);
        uint32_t X  = ((uint32_t)(r & 7)) << 4;
        unsigned char* base = g_Waug + (size_t)(nt * NK + kt) * B_TILE_BYTES;

        const float* cbase = &coeff[((size_t)o * D_IN + i0) * 7];
        const float* wbase = &w_base[(size_t)o * D_IN + i0];
#pragma unroll
        for (int d = 0; d < 4; d++) {
            const float* c = cbase + d * 7;
            uint4 v = make_uint4(h2(c[0], c[1]), h2(c[2], c[3]),
                                 h2(c[4], c[5]), h2(c[6], wbase[d]));
            *reinterpret_cast<uint4*>(base + ((u0 + d * 16) ^ X)) = v;
        }
    }
}

__global__ void reset_ctr_kernel() { g_tile_ctr = 0; }

// ---------------------------------------------------------------------------
// Persistent GEMM: 128x128 tiles via atomic work stealing, BK=64, 3-stage
// cp.async, 256 threads, 2 CTAs/SM, warp grid 2m x 4n (warp tile 64x32),
// ldmatrix.x4 + mma.m16n8k16.f16.f32.
// ---------------------------------------------------------------------------
__device__ __forceinline__ void cp_async16(uint32_t saddr, const void* gmem) {
    asm volatile("cp.async.cg.shared.global [%0], [%1], 16;\n"
                 :: "r"(saddr), "l"(gmem));
}
#define CP_COMMIT() asm volatile("cp.async.commit_group;\n" ::: "memory")
#define CP_WAIT1()  asm volatile("cp.async.wait_group 1;\n" ::: "memory")

__device__ __forceinline__ void ldsm_x4(unsigned& r0, unsigned& r1,
                                        unsigned& r2, unsigned& r3, uint32_t a) {
    asm volatile("ldmatrix.sync.aligned.m8n8.x4.shared.b16 {%0,%1,%2,%3}, [%4];"
                 : "=r"(r0), "=r"(r1), "=r"(r2), "=r"(r3) : "r"(a));
}

__device__ __forceinline__ void mma_f16(float* d, const unsigned* a, const unsigned* b) {
    asm volatile(
        "mma.sync.aligned.m16n8k16.row.col.f32.f16.f16.f32 "
        "{%0,%1,%2,%3}, {%4,%5,%6,%7}, {%8,%9}, {%0,%1,%2,%3};"
        : "+f"(d[0]), "+f"(d[1]), "+f"(d[2]), "+f"(d[3])
        : "r"(a[0]), "r"(a[1]), "r"(a[2]), "r"(a[3]), "r"(b[0]), "r"(b[1]));
}

__global__ __launch_bounds__(256, 2)
void gemm_kernel(const float* __restrict__ bias, float* __restrict__ C) {
    extern __shared__ __align__(128) unsigned char dyn[];
    __shared__ int s_tile;

    const int tid  = threadIdx.x;
    const int warp = tid >> 5;
    const int lane = tid & 31;
    const int wm   = (warp >> 2) * 64;   // 2 warps along M
    const int wn   = (warp & 3) * 32;    // 4 warps along N
    const int g    = lane >> 2;
    const int tg   = lane & 3;
    const int q    = lane >> 3;          // ldmatrix quad id
    const int li   = lane & 7;

    const uint32_t smem0 = (uint32_t)__cvta_generic_to_shared(dyn);

    // A frag geometry: mat0 rows m..m+7 @k, mat1 m+8..15 @k, mat2/3 same @k+8
    const int rowA = wm + (q & 1) * 8 + li;
    const uint32_t colA = (uint32_t)((q >> 1) * 16);
    const uint32_t XA = (uint32_t)((rowA & 7) << 4);
    // B frag pair (nt,nt+1): mat0 rows n..n+7 @k, mat1 @k+8, mat2/3 rows n+8..15
    const int rowB = wn + (q >> 1) * 8 + li;
    const uint32_t colB = (uint32_t)((q & 1) * 16);
    const uint32_t XB = (uint32_t)((rowB & 7) << 4);

    const unsigned char* gA;
    const unsigned char* gB;

    auto load_stage = [&](int s, int kt) {
        uint32_t As = smem0 + s * STAGE_BYTES;
        uint32_t Bs = As + A_TILE_BYTES;
        const unsigned char* At = gA + (size_t)kt * A_TILE_BYTES;
        const unsigned char* Bt = gB + (size_t)kt * B_TILE_BYTES;
#pragma unroll
        for (int i = 0; i < 4; i++) {
            int c = tid + i * 256;
            cp_async16(As + c * 16, At + c * 16);
        }
#pragma unroll
        for (int i = 0; i < 4; i++) {
            int c = tid + i * 256;
            cp_async16(Bs + c * 16, Bt + c * 16);
        }
    };

    // first tile
    if (tid == 0) s_tile = (int)atomicAdd(&g_tile_ctr, 1u);
    __syncthreads();
    int tile = s_tile;
    if (tile >= N_TILES) return;
    int cur_mt = tile >> 3, cur_nt = tile & 7;
    gA = g_Aaug + (size_t)cur_mt * NK * A_TILE_BYTES;
    gB = g_Waug + (size_t)cur_nt * NK * B_TILE_BYTES;
    load_stage(0, 0); CP_COMMIT();
    load_stage(1, 1); CP_COMMIT();

    while (true) {
        float acc[4][4][4];
#pragma unroll
        for (int mt = 0; mt < 4; mt++)
#pragma unroll
            for (int nt = 0; nt < 4; nt++)
#pragma unroll
                for (int r = 0; r < 4; r++) acc[mt][nt][r] = 0.f;

        int s = 0;
        for (int kt = 0; kt < NK; kt++) {
            CP_WAIT1();
            __syncthreads();

            const uint32_t As = smem0 + s * STAGE_BYTES;
            const uint32_t Bs = As + A_TILE_BYTES;

#pragma unroll
            for (int ks = 0; ks < 4; ks++) {
                const uint32_t kb = (uint32_t)(ks * 32);
                unsigned af[4][4];
                unsigned bf[4][2];
#pragma unroll
                for (int mt = 0; mt < 4; mt++)
                    ldsm_x4(af[mt][0], af[mt][1], af[mt][2], af[mt][3],
                            As + (uint32_t)((rowA + mt * 16) << 7) + ((kb + colA) ^ XA));
#pragma unroll
                for (int np = 0; np < 2; np++)
                    ldsm_x4(bf[np * 2][0], bf[np * 2][1],
                            bf[np * 2 + 1][0], bf[np * 2 + 1][1],
                            Bs + (uint32_t)((rowB + np * 16) << 7) + ((kb + colB) ^ XB));
#pragma unroll
                for (int mt = 0; mt < 4; mt++)
#pragma unroll
                    for (int nt = 0; nt < 4; nt++)
                        mma_f16(acc[mt][nt], af[mt], bf[nt]);
            }

            if (kt + 2 < NK) load_stage((kt + 2) % STAGES, kt + 2);
            CP_COMMIT();
            s = (s + 1 == STAGES) ? 0 : s + 1;
        }

        // all warps done reading smem of this tile before refilling
        __syncthreads();
        if (tid == 0) s_tile = (int)atomicAdd(&g_tile_ctr, 1u);
        __syncthreads();
        int next = s_tile;

        const int bm = cur_mt * BM;
        const int bn = cur_nt * BN;

        // start next tile's first two stages before the epilogue
        if (next < N_TILES) {
            cur_mt = next >> 3; cur_nt = next & 7;
            gA = g_Aaug + (size_t)cur_mt * NK * A_TILE_BYTES;
            gB = g_Waug + (size_t)cur_nt * NK * B_TILE_BYTES;
            load_stage(0, 0); CP_COMMIT();
            load_stage(1, 1); CP_COMMIT();
        }

        // epilogue for finished tile
#pragma unroll
        for (int mt = 0; mt < 4; mt++) {
#pragma unroll
            for (int nt = 0; nt < 4; nt++) {
                int m0 = bm + wm + mt * 16 + g;
                int n0 = bn + wn + nt * 8 + tg * 2;
                float bs0 = __ldg(&bias[n0]);
                float bs1 = __ldg(&bias[n0 + 1]);
                float2 v0 = make_float2(acc[mt][nt][0] + bs0, acc[mt][nt][1] + bs1);
                float2 v1 = make_float2(acc[mt][nt][2] + bs0, acc[mt][nt][3] + bs1);
                *reinterpret_cast<float2*>(&C[(size_t)m0 * N_DIM + n0]) = v0;
                *reinterpret_cast<float2*>(&C[(size_t)(m0 + 8) * N_DIM + n0]) = v1;
            }
        }

        if (next >= N_TILES) break;
    }
}

// ---------------------------------------------------------------------------
// Launch
// ---------------------------------------------------------------------------
extern "C" void kernel_launch(void* const* d_in, const int* in_sizes, int n_in,
                              void* d_out, int out_size) {
    const float* x      = (const float*)d_in[0];
    const float* coeff  = (const float*)d_in[1];
    const float* w_base = (const float*)d_in[2];
    const float* bias   = (const float*)d_in[3];
    float* out = (float*)d_out;

    cudaFuncSetAttribute(gemm_kernel,
                         cudaFuncAttributeMaxDynamicSharedMemorySize, DYN_BYTES);

    reset_ctr_kernel<<<1, 1>>>();
    pack_kernel<<<PACK_A_BLOCKS + PACK_W_BLOCKS, 256>>>(x, coeff, w_base);
    gemm_kernel<<<GRID_CTAS, 256, DYN_BYTES>>>(bias, out);
}

// round 9
// speedup vs baseline: 1.0539x; 1.0539x over previous
#include <cuda_runtime.h>
#include <cuda_fp16.h>
#include <cstdint>

// ---------------------------------------------------------------------------
// BSplineKAN as one augmented fp16 GEMM (fp32 accumulate) on mma.sync:
//   A[n, i*8+j] = basis_j(clip(x[n,i]))  (j<7),  silu(clip(x[n,i]))  (j==7)
//   W[o, i*8+j] = coeff[o,i,j]           (j<7),  w_base[o,i]         (j==7)
//   out = A (8192x8192) @ W^T (1024x8192) + bias
// SW128-swizzled K-major tile images; ldmatrix.x4; 128x128 tiles, split-K4
// with deterministic last-finisher reduction (fixed split-order summation).
// ---------------------------------------------------------------------------

#define M_DIM 8192
#define N_DIM 1024
#define D_IN  1024
#define K_DIM (D_IN * 8)      // 8192 fp16 elements

#define BM 128
#define BN 128
#define BK 64                 // 64 fp16 = 128B row
#define STAGES 3
#define NK (K_DIM / BK)       // 128 total ktiles
#define SPLITK 4
#define NK_UNIT (NK / SPLITK) // 32 ktiles per unit
#define TILES_M (M_DIM / BM)  // 64
#define TILES_N (N_DIM / BN)  // 8
#define N_TILES (TILES_M * TILES_N)  // 512

#define A_TILE_BYTES (BM * 128)   // 16384
#define B_TILE_BYTES (BN * 128)   // 16384
#define STAGE_BYTES  (A_TILE_BYTES + B_TILE_BYTES)  // 32768
#define DYN_BYTES    (STAGES * STAGE_BYTES)         // 98304 -> 2 CTAs/SM

__device__ __align__(128) unsigned char g_Aaug[(size_t)M_DIM * K_DIM * 2];  // 128MB
__device__ __align__(128) unsigned char g_Waug[(size_t)N_DIM * K_DIM * 2];  // 16MB
// partial accumulators: [tile][split][chunk(16)][tid(256)] float4  = 128MB
__device__ __align__(128) float4 g_part[(size_t)N_TILES * SPLITK * 16 * 256];
__device__ unsigned g_tickets[N_TILES];

// ---------------------------------------------------------------------------
// Cubic B-spline basis, literal Cox-de Boor matching the reference exactly
// (EPS-guarded repeated knots; x==1 edge yields all-zero basis as in ref).
// Grid: [-1,-1,-1,-1,-0.5,0,0.5,1,1,1,1]; all reciprocals compile-time.
// ---------------------------------------------------------------------------
__device__ __forceinline__ void bspline7(float x, float b[7]) {
    const float G[11] = {-1.f,-1.f,-1.f,-1.f,-0.5f,0.f,0.5f,1.f,1.f,1.f,1.f};
    float c0[10];
    c0[0] = 0.f; c0[1] = 0.f; c0[2] = 0.f;
    c0[3] = (x >= -1.0f && x < -0.5f) ? 1.f : 0.f;
    c0[4] = (x >= -0.5f && x <  0.0f) ? 1.f : 0.f;
    c0[5] = (x >=  0.0f && x <  0.5f) ? 1.f : 0.f;
    c0[6] = (x >=  0.5f && x <  1.0f) ? 1.f : 0.f;
    c0[7] = 0.f; c0[8] = 0.f;
    c0[9] = (x == 1.0f) ? 1.f : 0.f;

    const float INV_EPS = 1e8f;
    const float H = 2.0f, O = 1.0f, T = 0.66666669f;

    const float L1[9] = {INV_EPS,INV_EPS,INV_EPS,H,H,H,H,INV_EPS,INV_EPS};
    const float R1[9] = {INV_EPS,INV_EPS,H,H,H,H,INV_EPS,INV_EPS,INV_EPS};
    float c1[9];
#pragma unroll
    for (int t = 0; t < 9; t++)
        c1[t] = ((x - G[t]) * L1[t]) * c0[t] + ((G[t + 2] - x) * R1[t]) * c0[t + 1];

    const float L2[8] = {INV_EPS,INV_EPS,H,O,O,O,H,INV_EPS};
    const float R2[8] = {INV_EPS,H,O,O,O,H,INV_EPS,INV_EPS};
    float c2[8];
#pragma unroll
    for (int t = 0; t < 8; t++)
        c2[t] = ((x - G[t]) * L2[t]) * c1[t] + ((G[t + 3] - x) * R2[t]) * c1[t + 1];

    const float L3[7] = {INV_EPS,H,O,T,T,O,H};
    const float R3[7] = {H,O,T,T,O,H,INV_EPS};
#pragma unroll
    for (int t = 0; t < 7; t++)
        b[t] = ((x - G[t]) * L3[t]) * c2[t] + ((G[t + 4] - x) * R3[t]) * c2[t + 1];
}

__device__ __forceinline__ unsigned h2(float a, float b) {
    __half2 h = __floats2half2_rn(a, b);
    return *reinterpret_cast<unsigned*>(&h);
}

// ---------------------------------------------------------------------------
// Fused pack kernel: blocks [0, PACK_A_BLOCKS) pack A; rest pack W.
// Image: K-major fp16 rows (128B), SW128 swizzle u ^ ((r&7)<<4).
// ---------------------------------------------------------------------------
#define PACK_A_BLOCKS ((M_DIM * D_IN / 4) / 256)    // 8192
#define PACK_W_BLOCKS ((N_DIM * D_IN / 4) / 256)    // 1024

__global__ void pack_kernel(const float* __restrict__ x,
                            const float* __restrict__ coeff,
                            const float* __restrict__ w_base) {
    if (blockIdx.x < PACK_A_BLOCKS) {
        int idx = blockIdx.x * blockDim.x + threadIdx.x;
        int n  = idx >> 8;
        int i0 = (idx & 255) * 4;

        float4 xv = *reinterpret_cast<const float4*>(&x[(size_t)n * D_IN + i0]);
        float xc[4] = {fminf(fmaxf(xv.x, -1.f), 1.f), fminf(fmaxf(xv.y, -1.f), 1.f),
                       fminf(fmaxf(xv.z, -1.f), 1.f), fminf(fmaxf(xv.w, -1.f), 1.f)};

        int mt = n >> 7, r = n & 127;
        int kt = i0 >> 3;
        uint32_t u0 = ((uint32_t)r << 7) + ((uint32_t)(i0 & 7) << 4);
        uint32_t X  = ((uint32_t)(r & 7)) << 4;
        unsigned char* base = g_Aaug + (size_t)(mt * NK + kt) * A_TILE_BYTES;

#pragma unroll
        for (int d = 0; d < 4; d++) {
            float b[7];
            bspline7(xc[d], b);
            float s = xc[d] / (1.0f + __expf(-xc[d]));
            uint4 v = make_uint4(h2(b[0], b[1]), h2(b[2], b[3]),
                                 h2(b[4], b[5]), h2(b[6], s));
            *reinterpret_cast<uint4*>(base + ((u0 + d * 16) ^ X)) = v;
        }
    } else {
        int idx = (blockIdx.x - PACK_A_BLOCKS) * blockDim.x + threadIdx.x;
        int o  = idx >> 8;
        int i0 = (idx & 255) * 4;

        int nt = o >> 7, r = o & 127;
        int kt = i0 >> 3;
        uint32_t u0 = ((uint32_t)r << 7) + ((uint32_t)(i0 & 7) << 4);
        uint32_t X  = ((uint32_t)(r & 7)) << 4;
        unsigned char* base = g_Waug + (size_t)(nt * NK + kt) * B_TILE_BYTES;

        const float* cbase = &coeff[((size_t)o * D_IN + i0) * 7];
        const float* wbase = &w_base[(size_t)o * D_IN + i0];
#pragma unroll
        for (int d = 0; d < 4; d++) {
            const float* c = cbase + d * 7;
            uint4 v = make_uint4(h2(c[0], c[1]), h2(c[2], c[3]),
                                 h2(c[4], c[5]), h2(c[6], wbase[d]));
            *reinterpret_cast<uint4*>(base + ((u0 + d * 16) ^ X)) = v;
        }
    }
}

__global__ void reset_kernel() {
    if (threadIdx.x < N_TILES) g_tickets[threadIdx.x] = 0;
}

// ---------------------------------------------------------------------------
// Split-K GEMM: grid (nt=8, mt=64, s=4); 256 threads; 2 CTAs/SM.
// Each CTA: 128x128 tile over 32 ktiles -> partial; last finisher reduces in
// fixed split order (deterministic) + bias and writes C.
// ---------------------------------------------------------------------------
__device__ __forceinline__ void cp_async16(uint32_t saddr, const void* gmem) {
    asm volatile("cp.async.cg.shared.global [%0], [%1], 16;\n"
                 :: "r"(saddr), "l"(gmem));
}
#define CP_COMMIT() asm volatile("cp.async.commit_group;\n" ::: "memory")
#define CP_WAIT1()  asm volatile("cp.async.wait_group 1;\n" ::: "memory")

__device__ __forceinline__ void ldsm_x4(unsigned& r0, unsigned& r1,
                                        unsigned& r2, unsigned& r3, uint32_t a) {
    asm volatile("ldmatrix.sync.aligned.m8n8.x4.shared.b16 {%0,%1,%2,%3}, [%4];"
                 : "=r"(r0), "=r"(r1), "=r"(r2), "=r"(r3) : "r"(a));
}

__device__ __forceinline__ void mma_f16(float* d, const unsigned* a, const unsigned* b) {
    asm volatile(
        "mma.sync.aligned.m16n8k16.row.col.f32.f16.f16.f32 "
        "{%0,%1,%2,%3}, {%4,%5,%6,%7}, {%8,%9}, {%0,%1,%2,%3};"
        : "+f"(d[0]), "+f"(d[1]), "+f"(d[2]), "+f"(d[3])
        : "r"(a[0]), "r"(a[1]), "r"(a[2]), "r"(a[3]), "r"(b[0]), "r"(b[1]));
}

__global__ __launch_bounds__(256, 2)
void gemm_kernel(const float* __restrict__ bias, float* __restrict__ C) {
    extern __shared__ __align__(128) unsigned char dyn[];
    __shared__ unsigned s_ticket;

    const int tid  = threadIdx.x;
    const int warp = tid >> 5;
    const int lane = tid & 31;
    const int tile = (int)blockIdx.y * TILES_N + (int)blockIdx.x;
    const int sk   = (int)blockIdx.z;
    const int kt0  = sk * NK_UNIT;
    const int bm   = (int)blockIdx.y * BM;
    const int bn   = (int)blockIdx.x * BN;
    const int wm   = (warp >> 2) * 64;
    const int wn   = (warp & 3) * 32;
    const int g    = lane >> 2;
    const int tg   = lane & 3;
    const int q    = lane >> 3;
    const int li   = lane & 7;

    const uint32_t smem0 = (uint32_t)__cvta_generic_to_shared(dyn);

    const unsigned char* gA = g_Aaug + (size_t)blockIdx.y * NK * A_TILE_BYTES;
    const unsigned char* gB = g_Waug + (size_t)blockIdx.x * NK * B_TILE_BYTES;

    const int rowA = wm + (q & 1) * 8 + li;
    const uint32_t colA = (uint32_t)((q >> 1) * 16);
    const uint32_t XA = (uint32_t)((rowA & 7) << 4);
    const int rowB = wn + (q >> 1) * 8 + li;
    const uint32_t colB = (uint32_t)((q & 1) * 16);
    const uint32_t XB = (uint32_t)((rowB & 7) << 4);

    float acc[4][4][4];
#pragma unroll
    for (int mt = 0; mt < 4; mt++)
#pragma unroll
        for (int nt = 0; nt < 4; nt++)
#pragma unroll
            for (int r = 0; r < 4; r++) acc[mt][nt][r] = 0.f;

    auto load_stage = [&](int s, int kt) {
        uint32_t As = smem0 + s * STAGE_BYTES;
        uint32_t Bs = As + A_TILE_BYTES;
        const unsigned char* At = gA + (size_t)kt * A_TILE_BYTES;
        const unsigned char* Bt = gB + (size_t)kt * B_TILE_BYTES;
#pragma unroll
        for (int i = 0; i < 4; i++) {
            int c = tid + i * 256;
            cp_async16(As + c * 16, At + c * 16);
        }
#pragma unroll
        for (int i = 0; i < 4; i++) {
            int c = tid + i * 256;
            cp_async16(Bs + c * 16, Bt + c * 16);
        }
    };

    load_stage(0, kt0);     CP_COMMIT();
    load_stage(1, kt0 + 1); CP_COMMIT();

    int s = 0;
    for (int k = 0; k < NK_UNIT; k++) {
        CP_WAIT1();
        __syncthreads();

        const uint32_t As = smem0 + s * STAGE_BYTES;
        const uint32_t Bs = As + A_TILE_BYTES;

#pragma unroll
        for (int ks = 0; ks < 4; ks++) {
            const uint32_t kb = (uint32_t)(ks * 32);
            unsigned af[4][4];
            unsigned bf[4][2];
#pragma unroll
            for (int mt = 0; mt < 4; mt++)
                ldsm_x4(af[mt][0], af[mt][1], af[mt][2], af[mt][3],
                        As + (uint32_t)((rowA + mt * 16) << 7) + ((kb + colA) ^ XA));
#pragma unroll
            for (int np = 0; np < 2; np++)
                ldsm_x4(bf[np * 2][0], bf[np * 2][1],
                        bf[np * 2 + 1][0], bf[np * 2 + 1][1],
                        Bs + (uint32_t)((rowB + np * 16) << 7) + ((kb + colB) ^ XB));
#pragma unroll
            for (int mt = 0; mt < 4; mt++)
#pragma unroll
                for (int nt = 0; nt < 4; nt++)
                    mma_f16(acc[mt][nt], af[mt], bf[nt]);
        }

        if (k + 2 < NK_UNIT) load_stage((k + 2) % STAGES, kt0 + k + 2);
        CP_COMMIT();
        s = (s + 1 == STAGES) ? 0 : s + 1;
    }

    // --- write this split's partial (chunk-major coalesced layout) ---
    // chunk c = mt*4+nt; address = part[(tile*SPLITK + sk)*4096 + c*256 + tid]
    float4* myp = &g_part[((size_t)tile * SPLITK + sk) * 4096];
#pragma unroll
    for (int mt = 0; mt < 4; mt++)
#pragma unroll
        for (int nt = 0; nt < 4; nt++) {
            int c = mt * 4 + nt;
            myp[c * 256 + tid] = make_float4(acc[mt][nt][0], acc[mt][nt][1],
                                             acc[mt][nt][2], acc[mt][nt][3]);
        }

    __threadfence();
    __syncthreads();
    if (tid == 0) s_ticket = atomicAdd(&g_tickets[tile], 1u);
    __syncthreads();
    if (s_ticket != SPLITK - 1) return;   // not last finisher
    __threadfence();

    // --- last finisher: reduce in fixed split order 0..3 (deterministic) ---
#pragma unroll
    for (int mt = 0; mt < 4; mt++) {
#pragma unroll
        for (int nt = 0; nt < 4; nt++) {
            int c = mt * 4 + nt;
            float4 sum;
            {
                const float4* p0 = &g_part[((size_t)tile * SPLITK + 0) * 4096];
                if (sk == 0) sum = make_float4(acc[mt][nt][0], acc[mt][nt][1],
                                               acc[mt][nt][2], acc[mt][nt][3]);
                else         sum = __ldcg(&p0[c * 256 + tid]);
            }
#pragma unroll
            for (int sp = 1; sp < SPLITK; sp++) {
                float4 v;
                if (sp == sk) v = make_float4(acc[mt][nt][0], acc[mt][nt][1],
                                              acc[mt][nt][2], acc[mt][nt][3]);
                else {
                    const float4* pp = &g_part[((size_t)tile * SPLITK + sp) * 4096];
                    v = __ldcg(&pp[c * 256 + tid]);
                }
                sum.x += v.x; sum.y += v.y; sum.z += v.z; sum.w += v.w;
            }

            int m0 = bm + wm + mt * 16 + g;
            int n0 = bn + wn + nt * 8 + tg * 2;
            float bs0 = __ldg(&bias[n0]);
            float bs1 = __ldg(&bias[n0 + 1]);
            float2 v0 = make_float2(sum.x + bs0, sum.y + bs1);
            float2 v1 = make_float2(sum.z + bs0, sum.w + bs1);
            *reinterpret_cast<float2*>(&C[(size_t)m0 * N_DIM + n0]) = v0;
            *reinterpret_cast<float2*>(&C[(size_t)(m0 + 8) * N_DIM + n0]) = v1;
        }
    }
}

// ---------------------------------------------------------------------------
// Launch
// ---------------------------------------------------------------------------
extern "C" void kernel_launch(void* const* d_in, const int* in_sizes, int n_in,
                              void* d_out, int out_size) {
    const float* x      = (const float*)d_in[0];
    const float* coeff  = (const float*)d_in[1];
    const float* w_base = (const float*)d_in[2];
    const float* bias   = (const float*)d_in[3];
    float* out = (float*)d_out;

    cudaFuncSetAttribute(gemm_kernel,
                         cudaFuncAttributeMaxDynamicSharedMemorySize, DYN_BYTES);

    reset_kernel<<<1, N_TILES>>>();
    pack_kernel<<<PACK_A_BLOCKS + PACK_W_BLOCKS, 256>>>(x, coeff, w_base);
    gemm_kernel<<<dim3(TILES_N, TILES_M, SPLITK), 256, DYN_BYTES>>>(bias, out);
}